// round 12
// baseline (speedup 1.0000x reference)
#include <cuda_runtime.h>
#include <cstdint>

// ---------------------------------------------------------------------------
// fp4 (bitsandbytes) dequant + GEMV:  y[4, M] = x[4, N] @ W[M, N]^T + bias
//   qweight: numel/2 int32, each holding ONE byte (two nibbles, hi first)
//   absmax : per-64-element block scale; code: 16-entry codebook
//
// R5/R11 mapping: warp owns a contiguous 64-n "step"; lane l takes the packed
// byte at int32 index (step*32 + l), i.e. n = 2l, 2l+1. x loads LDG.64
// lane-consecutive (L1-resident), absmax preloaded to smem (uniform LDS).
// R12 changes:
//   * q prefetch distance 2 (bq/bn/bf register rotation) -> 2x q bytes in
//     flight per warp vs R11.
//   * NO second kernel: out zeroed by cudaMemsetAsync (graph node), each
//     split block atomicAdds its partial (REDG); bias folded into split 0.
//     Deterministic: 0+a+b == 0+b+a bitwise for IEEE fp32.
// 4 rows/warp, 4 warps/block, N split in 2 halves; grid (2,512) = 1024
// blocks, all co-resident in one wave at 7 CTAs/SM.
// ---------------------------------------------------------------------------

constexpr int MD = 8192, ND = 8192;
constexpr int NSPLIT = 2;
constexpr int NHALF  = ND / NSPLIT;     // 4096 n per block
constexpr int STEPS  = NHALF / 64;      // 64 steps (one absmax block each)
constexpr int RW = 4;                   // rows per warp
constexpr int WPB = 4;                  // warps per block (128 threads)
constexpr int RPB = RW * WPB;           // 16 rows per block

static __device__ __forceinline__ unsigned long long pk2(float lo, float hi) {
    unsigned long long r;
    asm("mov.b64 %0, {%1, %2};" : "=l"(r) : "f"(lo), "f"(hi));
    return r;
}
static __device__ __forceinline__ void up2(unsigned long long v, float& lo, float& hi) {
    asm("mov.b64 {%0, %1}, %2;" : "=f"(lo), "=f"(hi) : "l"(v));
}
static __device__ __forceinline__ unsigned long long f2fma(unsigned long long a,
                                                           unsigned long long b,
                                                           unsigned long long c) {
    unsigned long long d;
    asm("fma.rn.f32x2 %0, %1, %2, %3;" : "=l"(d) : "l"(a), "l"(b), "l"(c));
    return d;
}
static __device__ __forceinline__ unsigned long long f2add(unsigned long long a,
                                                           unsigned long long b) {
    unsigned long long d;
    asm("add.rn.f32x2 %0, %1, %2;" : "=l"(d) : "l"(a), "l"(b));
    return d;
}

__global__ void __launch_bounds__(128, 7)
fp4_main(const float* __restrict__ x, const int* __restrict__ qw,
         const float* __restrict__ am, const float* __restrict__ code,
         const float* __restrict__ bias, float* __restrict__ out)
{
    __shared__ float am_sm[RPB * STEPS];   // [row-in-block][step], 4 KB

    const int lane = threadIdx.x & 31;
    const int wid  = threadIdx.x >> 5;
    const int split   = blockIdx.x;            // 0 or 1
    const int rowbase = blockIdx.y * RPB;
    const int row0    = rowbase + wid * RW;
    const int n0      = split * NHALF;

    // Register-resident codebook: lane l holds code[l & 15]; decode via shfl.
    const float creg = code[lane & 15];

    // ---- absmax preload: RPB*STEPS = 1024 floats, coalesced ----
    for (int k = threadIdx.x; k < RPB * STEPS; k += 128) {
        const int r  = k >> 6;          // row in block
        const int st = k & 63;          // step
        am_sm[k] = am[(rowbase + r) * (ND / 64) + split * (NHALF / 64) + st];
    }
    __syncthreads();

    // Per-row q streams for this N-half.
    const int* q0 = qw + row0 * (ND / 2) + split * (NHALF / 2);
    const float2* x0 = reinterpret_cast<const float2*>(x + 0 * ND + n0);
    const float2* x1 = reinterpret_cast<const float2*>(x + 1 * ND + n0);
    const float2* x2 = reinterpret_cast<const float2*>(x + 2 * ND + n0);
    const float2* x3 = reinterpret_cast<const float2*>(x + 3 * ND + n0);

    unsigned long long a01[RW] = {0, 0, 0, 0};
    unsigned long long a23[RW] = {0, 0, 0, 0};

    // ---- q prefetch, distance 2 ----
    int bq[RW], bn[RW];
#pragma unroll
    for (int r = 0; r < RW; r++) {
        bq[r] = __ldcs(q0 + r * (ND / 2) + lane);           // step 0
        bn[r] = __ldcs(q0 + r * (ND / 2) + 32 + lane);      // step 1
    }

#pragma unroll 2
    for (int step = 0; step < STEPS; ++step) {
        // Prefetch step+2's q bytes (clamped on the tail; redundant loads).
        const int pcol = (step < STEPS - 2 ? step + 2 : step) * 32 + lane;
        int bf[RW];
#pragma unroll
        for (int r = 0; r < RW; r++) bf[r] = __ldcs(q0 + r * (ND / 2) + pcol);

        const int col = step * 32 + lane;
        const float2 v0 = __ldg(&x0[col]);
        const float2 v1 = __ldg(&x1[col]);
        const float2 v2 = __ldg(&x2[col]);
        const float2 v3 = __ldg(&x3[col]);
        const unsigned long long xe01 = pk2(v0.x, v1.x);   // n even, batches 0,1
        const unsigned long long xo01 = pk2(v0.y, v1.y);   // n odd
        const unsigned long long xe23 = pk2(v2.x, v3.x);
        const unsigned long long xo23 = pk2(v2.y, v3.y);

#pragma unroll
        for (int r = 0; r < RW; r++) {
            const int   b = bq[r];                                  // one byte
            const float s = am_sm[(wid * RW + r) * STEPS + step];   // uniform LDS
            const float chi = __shfl_sync(0xffffffffu, creg, b >> 4);   // n = 2l
            const float clo = __shfl_sync(0xffffffffu, creg, b & 15);   // n = 2l+1
            const float w0 = chi * s;
            const float w1 = clo * s;
            const unsigned long long s0 = pk2(w0, w0);
            const unsigned long long s1 = pk2(w1, w1);
            a01[r] = f2fma(s0, xe01, a01[r]);
            a01[r] = f2fma(s1, xo01, a01[r]);
            a23[r] = f2fma(s0, xe23, a23[r]);
            a23[r] = f2fma(s1, xo23, a23[r]);
        }

#pragma unroll
        for (int r = 0; r < RW; r++) { bq[r] = bn[r]; bn[r] = bf[r]; }
    }

    // Butterfly reduction over lanes (packed f32x2 adds).
#pragma unroll
    for (int r = 0; r < RW; r++) {
#pragma unroll
        for (int off = 16; off > 0; off >>= 1) {
            a01[r] = f2add(a01[r], __shfl_xor_sync(0xffffffffu, a01[r], off));
            a23[r] = f2add(a23[r], __shfl_xor_sync(0xffffffffu, a23[r], off));
        }
    }

    // Accumulate into out (zeroed by the memset graph node). REDG no-return
    // atomics; exactly two adds per output in commutative order ->
    // bit-deterministic. Bias contributed once, by split 0.
#pragma unroll
    for (int r = 0; r < RW; r++) {
        if (lane == r) {
            const int row = row0 + r;
            float y0, y1, y2, y3;
            up2(a01[r], y0, y1);
            up2(a23[r], y2, y3);
            if (split == 0) {
                const float bb = bias[row];
                y0 += bb; y1 += bb; y2 += bb; y3 += bb;
            }
            atomicAdd(&out[0 * MD + row], y0);
            atomicAdd(&out[1 * MD + row], y1);
            atomicAdd(&out[2 * MD + row], y2);
            atomicAdd(&out[3 * MD + row], y3);
        }
    }
}

extern "C" void kernel_launch(void* const* d_in, const int* in_sizes, int n_in,
                              void* d_out, int out_size)
{
    const float* x    = (const float*)d_in[0];
    const int*   qw   = (const int*)d_in[1];
    const float* am   = (const float*)d_in[2];
    const float* code = (const float*)d_in[3];
    const float* bias = (const float*)d_in[4];
    float*       out  = (float*)d_out;

    cudaMemsetAsync(out, 0, (size_t)out_size * sizeof(float));
    dim3 grid(NSPLIT, MD / RPB);              // (2, 512) = 1024 blocks
    fp4_main<<<grid, WPB * 32>>>(x, qw, am, code, bias, out);
}

// round 13
// speedup vs baseline: 1.0588x; 1.0588x over previous
#include <cuda_runtime.h>
#include <cstdint>

// ---------------------------------------------------------------------------
// fp4 (bitsandbytes) dequant + GEMV:  y[4, M] = x[4, N] @ W[M, N]^T + bias
//   qweight: numel/2 int32, each holding ONE byte (two nibbles, hi first)
//   absmax : per-64-element block scale; code: 16-entry codebook
//
// Mapping (best measured, R11): warp owns a contiguous 64-n "step"; lane l
// takes the packed byte at int32 index (step*32 + l), i.e. n = 2l, 2l+1.
//   * x loads LDG.64 lane-consecutive (L1-resident 128KB working set)
//   * q loaded with __ldcs (streaming, evict-first), prefetch distance 1
//   * absmax preloaded to smem per block (uniform LDS broadcast in loop)
//   * __launch_bounds__(128,7): 7 CTAs/SM -> all 1024 blocks in ONE wave
// Epilogue (R12): out zeroed by cudaMemsetAsync graph node; each split block
// atomicAdds its partial (REDG no-return); bias folded into split 0.
// Deterministic: exactly two commutative IEEE adds per output.
// ---------------------------------------------------------------------------

constexpr int MD = 8192, ND = 8192;
constexpr int NSPLIT = 2;
constexpr int NHALF  = ND / NSPLIT;     // 4096 n per block
constexpr int STEPS  = NHALF / 64;      // 64 steps (one absmax block each)
constexpr int RW = 4;                   // rows per warp
constexpr int WPB = 4;                  // warps per block (128 threads)
constexpr int RPB = RW * WPB;           // 16 rows per block

static __device__ __forceinline__ unsigned long long pk2(float lo, float hi) {
    unsigned long long r;
    asm("mov.b64 %0, {%1, %2};" : "=l"(r) : "f"(lo), "f"(hi));
    return r;
}
static __device__ __forceinline__ void up2(unsigned long long v, float& lo, float& hi) {
    asm("mov.b64 {%0, %1}, %2;" : "=f"(lo), "=f"(hi) : "l"(v));
}
static __device__ __forceinline__ unsigned long long f2fma(unsigned long long a,
                                                           unsigned long long b,
                                                           unsigned long long c) {
    unsigned long long d;
    asm("fma.rn.f32x2 %0, %1, %2, %3;" : "=l"(d) : "l"(a), "l"(b), "l"(c));
    return d;
}
static __device__ __forceinline__ unsigned long long f2add(unsigned long long a,
                                                           unsigned long long b) {
    unsigned long long d;
    asm("add.rn.f32x2 %0, %1, %2;" : "=l"(d) : "l"(a), "l"(b));
    return d;
}

__global__ void __launch_bounds__(128, 7)
fp4_main(const float* __restrict__ x, const int* __restrict__ qw,
         const float* __restrict__ am, const float* __restrict__ code,
         const float* __restrict__ bias, float* __restrict__ out)
{
    __shared__ float am_sm[RPB * STEPS];   // [row-in-block][step], 4 KB

    const int lane = threadIdx.x & 31;
    const int wid  = threadIdx.x >> 5;
    const int split   = blockIdx.x;            // 0 or 1
    const int rowbase = blockIdx.y * RPB;
    const int row0    = rowbase + wid * RW;
    const int n0      = split * NHALF;

    // Register-resident codebook: lane l holds code[l & 15]; decode via shfl.
    const float creg = code[lane & 15];

    // ---- absmax preload: RPB*STEPS = 1024 floats, coalesced ----
    for (int k = threadIdx.x; k < RPB * STEPS; k += 128) {
        const int r  = k >> 6;          // row in block
        const int st = k & 63;          // step
        am_sm[k] = am[(rowbase + r) * (ND / 64) + split * (NHALF / 64) + st];
    }
    __syncthreads();

    // Per-row q streams for this N-half.
    const int* q0 = qw + row0 * (ND / 2) + split * (NHALF / 2);
    const float2* x0 = reinterpret_cast<const float2*>(x + 0 * ND + n0);
    const float2* x1 = reinterpret_cast<const float2*>(x + 1 * ND + n0);
    const float2* x2 = reinterpret_cast<const float2*>(x + 2 * ND + n0);
    const float2* x3 = reinterpret_cast<const float2*>(x + 3 * ND + n0);

    unsigned long long a01[RW] = {0, 0, 0, 0};
    unsigned long long a23[RW] = {0, 0, 0, 0};

    // ---- q prefetch, distance 1 ----
    int bq[RW];
#pragma unroll
    for (int r = 0; r < RW; r++) bq[r] = __ldcs(q0 + r * (ND / 2) + lane);

#pragma unroll 2
    for (int step = 0; step < STEPS; ++step) {
        // Prefetch next step's q bytes (clamped on last iter; redundant load).
        const int ncol = (step < STEPS - 1 ? step + 1 : step) * 32 + lane;
        int bn[RW];
#pragma unroll
        for (int r = 0; r < RW; r++) bn[r] = __ldcs(q0 + r * (ND / 2) + ncol);

        const int col = step * 32 + lane;
        const float2 v0 = __ldg(&x0[col]);
        const float2 v1 = __ldg(&x1[col]);
        const float2 v2 = __ldg(&x2[col]);
        const float2 v3 = __ldg(&x3[col]);
        const unsigned long long xe01 = pk2(v0.x, v1.x);   // n even, batches 0,1
        const unsigned long long xo01 = pk2(v0.y, v1.y);   // n odd
        const unsigned long long xe23 = pk2(v2.x, v3.x);
        const unsigned long long xo23 = pk2(v2.y, v3.y);

#pragma unroll
        for (int r = 0; r < RW; r++) {
            const int   b = bq[r];                                  // one byte
            const float s = am_sm[(wid * RW + r) * STEPS + step];   // uniform LDS
            const float chi = __shfl_sync(0xffffffffu, creg, b >> 4);   // n = 2l
            const float clo = __shfl_sync(0xffffffffu, creg, b & 15);   // n = 2l+1
            const float w0 = chi * s;
            const float w1 = clo * s;
            const unsigned long long s0 = pk2(w0, w0);
            const unsigned long long s1 = pk2(w1, w1);
            a01[r] = f2fma(s0, xe01, a01[r]);
            a01[r] = f2fma(s1, xo01, a01[r]);
            a23[r] = f2fma(s0, xe23, a23[r]);
            a23[r] = f2fma(s1, xo23, a23[r]);
        }

#pragma unroll
        for (int r = 0; r < RW; r++) bq[r] = bn[r];
    }

    // Butterfly reduction over lanes (packed f32x2 adds).
#pragma unroll
    for (int r = 0; r < RW; r++) {
#pragma unroll
        for (int off = 16; off > 0; off >>= 1) {
            a01[r] = f2add(a01[r], __shfl_xor_sync(0xffffffffu, a01[r], off));
            a23[r] = f2add(a23[r], __shfl_xor_sync(0xffffffffu, a23[r], off));
        }
    }

    // Accumulate into out (zeroed by the memset graph node). REDG no-return
    // atomics; exactly two commutative adds per output -> bit-deterministic.
    // Bias contributed once, by split 0.
#pragma unroll
    for (int r = 0; r < RW; r++) {
        if (lane == r) {
            const int row = row0 + r;
            float y0, y1, y2, y3;
            up2(a01[r], y0, y1);
            up2(a23[r], y2, y3);
            if (split == 0) {
                const float bb = bias[row];
                y0 += bb; y1 += bb; y2 += bb; y3 += bb;
            }
            atomicAdd(&out[0 * MD + row], y0);
            atomicAdd(&out[1 * MD + row], y1);
            atomicAdd(&out[2 * MD + row], y2);
            atomicAdd(&out[3 * MD + row], y3);
        }
    }
}

extern "C" void kernel_launch(void* const* d_in, const int* in_sizes, int n_in,
                              void* d_out, int out_size)
{
    const float* x    = (const float*)d_in[0];
    const int*   qw   = (const int*)d_in[1];
    const float* am   = (const float*)d_in[2];
    const float* code = (const float*)d_in[3];
    const float* bias = (const float*)d_in[4];
    float*       out  = (float*)d_out;

    cudaMemsetAsync(out, 0, (size_t)out_size * sizeof(float));
    dim3 grid(NSPLIT, MD / RPB);              // (2, 512) = 1024 blocks
    fp4_main<<<grid, WPB * 32>>>(x, qw, am, code, bias, out);
}

// round 14
// speedup vs baseline: 1.0671x; 1.0078x over previous
#include <cuda_runtime.h>
#include <cstdint>

// ---------------------------------------------------------------------------
// fp4 (bitsandbytes) dequant + GEMV:  y[4, M] = x[4, N] @ W[M, N]^T + bias
//   qweight: numel/2 int32, each holding ONE byte (two nibbles, hi first)
//   absmax : per-64-element block scale; code: 16-entry codebook
//
// Mapping: warp owns a contiguous 64-n "step"; lane l takes the packed byte
// at int32 index (step*32 + l), i.e. n = 2l, 2l+1.
// R14: x staged per 512-col phase into smem ALREADY in batch-pair u64 form
// (xe01/xo01/xe23/xo23) -> inner loop x-side is 4 conflict-free LDS.64
// instead of 4 LDG.64 + 8 transpose movs. Removes ~12 instr + 4 L1
// wavefronts per step from every warp.
//   * q: __ldcs streaming loads, register prefetch distance 1
//   * absmax: preloaded to smem (uniform LDS broadcast)
//   * epilogue: out zeroed by cudaMemsetAsync; 2 commutative atomicAdds per
//     output (bit-deterministic); bias folded into split 0
//   * grid (2,512)=1024 blocks x 128 thr, 7 CTAs/SM -> single wave
// ---------------------------------------------------------------------------

constexpr int MD = 8192, ND = 8192;
constexpr int NSPLIT = 2;
constexpr int NHALF  = ND / NSPLIT;       // 4096 n per block
constexpr int CHALF  = NHALF / 2;         // 2048 int32 cols per row-half
constexpr int STEPS  = CHALF / 32;        // 64 steps (one absmax block each)
constexpr int RW = 4;                     // rows per warp
constexpr int WPB = 4;                    // warps per block (128 threads)
constexpr int RPB = RW * WPB;             // 16 rows per block
constexpr int PH_COLS = 512;              // staged cols per phase (16 KB)
constexpr int PHASES  = CHALF / PH_COLS;  // 4
constexpr int SPP     = PH_COLS / 32;     // 16 steps per phase

static __device__ __forceinline__ unsigned long long pk2(float lo, float hi) {
    unsigned long long r;
    asm("mov.b64 %0, {%1, %2};" : "=l"(r) : "f"(lo), "f"(hi));
    return r;
}
static __device__ __forceinline__ void up2(unsigned long long v, float& lo, float& hi) {
    asm("mov.b64 {%0, %1}, %2;" : "=f"(lo), "=f"(hi) : "l"(v));
}
static __device__ __forceinline__ unsigned long long f2fma(unsigned long long a,
                                                           unsigned long long b,
                                                           unsigned long long c) {
    unsigned long long d;
    asm("fma.rn.f32x2 %0, %1, %2, %3;" : "=l"(d) : "l"(a), "l"(b), "l"(c));
    return d;
}
static __device__ __forceinline__ unsigned long long f2add(unsigned long long a,
                                                           unsigned long long b) {
    unsigned long long d;
    asm("add.rn.f32x2 %0, %1, %2;" : "=l"(d) : "l"(a), "l"(b));
    return d;
}

__global__ void __launch_bounds__(128, 7)
fp4_main(const float* __restrict__ x, const int* __restrict__ qw,
         const float* __restrict__ am, const float* __restrict__ code,
         const float* __restrict__ bias, float* __restrict__ out)
{
    __shared__ float am_sm[RPB * STEPS];                  // 4 KB
    __shared__ unsigned long long xe01_sm[PH_COLS];       // 4 KB each
    __shared__ unsigned long long xo01_sm[PH_COLS];
    __shared__ unsigned long long xe23_sm[PH_COLS];
    __shared__ unsigned long long xo23_sm[PH_COLS];

    const int lane = threadIdx.x & 31;
    const int wid  = threadIdx.x >> 5;
    const int split   = blockIdx.x;            // 0 or 1
    const int rowbase = blockIdx.y * RPB;
    const int row0    = rowbase + wid * RW;
    const int n0      = split * NHALF;

    // Register-resident codebook: lane l holds code[l & 15]; decode via shfl.
    const float creg = code[lane & 15];

    // ---- absmax preload: RPB*STEPS = 1024 floats, coalesced ----
    for (int k = threadIdx.x; k < RPB * STEPS; k += 128) {
        const int r  = k >> 6;          // row in block
        const int st = k & 63;          // step
        am_sm[k] = am[(rowbase + r) * (ND / 64) + split * (NHALF / 64) + st];
    }

    // Per-row q streams for this N-half.
    const int* q0 = qw + row0 * (ND / 2) + split * CHALF;
    const float2* x0 = reinterpret_cast<const float2*>(x + 0 * ND + n0);
    const float2* x1 = reinterpret_cast<const float2*>(x + 1 * ND + n0);
    const float2* x2 = reinterpret_cast<const float2*>(x + 2 * ND + n0);
    const float2* x3 = reinterpret_cast<const float2*>(x + 3 * ND + n0);

    unsigned long long a01[RW] = {0, 0, 0, 0};
    unsigned long long a23[RW] = {0, 0, 0, 0};

    // ---- q prefetch, distance 1 ----
    int bq[RW];
#pragma unroll
    for (int r = 0; r < RW; r++) bq[r] = __ldcs(q0 + r * (ND / 2) + lane);

    for (int ph = 0; ph < PHASES; ++ph) {
        // ---- stage this phase's x cols in batch-pair form ----
        const int cbase = ph * PH_COLS;
#pragma unroll
        for (int kk = 0; kk < PH_COLS / 128; ++kk) {
            const int k = kk * 128 + threadIdx.x;
            const int c = cbase + k;
            const float2 v0 = x0[c];
            const float2 v1 = x1[c];
            const float2 v2 = x2[c];
            const float2 v3 = x3[c];
            xe01_sm[k] = pk2(v0.x, v1.x);
            xo01_sm[k] = pk2(v0.y, v1.y);
            xe23_sm[k] = pk2(v2.x, v3.x);
            xo23_sm[k] = pk2(v2.y, v3.y);
        }
        __syncthreads();   // x phase (and, on ph==0, am_sm) ready

#pragma unroll 2
        for (int t = 0; t < SPP; ++t) {
            const int step = ph * SPP + t;
            // Prefetch next step's q bytes (clamped on the very last step).
            const int ncol = (step < STEPS - 1 ? step + 1 : step) * 32 + lane;
            int bn[RW];
#pragma unroll
            for (int r = 0; r < RW; r++) bn[r] = __ldcs(q0 + r * (ND / 2) + ncol);

            const int k = t * 32 + lane;
            const unsigned long long xe01 = xe01_sm[k];   // conflict-free LDS.64
            const unsigned long long xo01 = xo01_sm[k];
            const unsigned long long xe23 = xe23_sm[k];
            const unsigned long long xo23 = xo23_sm[k];

#pragma unroll
            for (int r = 0; r < RW; r++) {
                const int   b = bq[r];                                  // one byte
                const float s = am_sm[(wid * RW + r) * STEPS + step];   // uniform
                const float chi = __shfl_sync(0xffffffffu, creg, b >> 4);   // n=2l
                const float clo = __shfl_sync(0xffffffffu, creg, b & 15);   // n=2l+1
                const float w0 = chi * s;
                const float w1 = clo * s;
                const unsigned long long s0 = pk2(w0, w0);
                const unsigned long long s1 = pk2(w1, w1);
                a01[r] = f2fma(s0, xe01, a01[r]);
                a01[r] = f2fma(s1, xo01, a01[r]);
                a23[r] = f2fma(s0, xe23, a23[r]);
                a23[r] = f2fma(s1, xo23, a23[r]);
            }

#pragma unroll
            for (int r = 0; r < RW; r++) bq[r] = bn[r];
        }
        __syncthreads();   // all warps done with this phase before restage
    }

    // Butterfly reduction over lanes (packed f32x2 adds).
#pragma unroll
    for (int r = 0; r < RW; r++) {
#pragma unroll
        for (int off = 16; off > 0; off >>= 1) {
            a01[r] = f2add(a01[r], __shfl_xor_sync(0xffffffffu, a01[r], off));
            a23[r] = f2add(a23[r], __shfl_xor_sync(0xffffffffu, a23[r], off));
        }
    }

    // Accumulate into out (zeroed by the memset graph node). Exactly two
    // commutative IEEE adds per output -> bit-deterministic. Bias once (split 0).
#pragma unroll
    for (int r = 0; r < RW; r++) {
        if (lane == r) {
            const int row = row0 + r;
            float y0, y1, y2, y3;
            up2(a01[r], y0, y1);
            up2(a23[r], y2, y3);
            if (split == 0) {
                const float bb = bias[row];
                y0 += bb; y1 += bb; y2 += bb; y3 += bb;
            }
            atomicAdd(&out[0 * MD + row], y0);
            atomicAdd(&out[1 * MD + row], y1);
            atomicAdd(&out[2 * MD + row], y2);
            atomicAdd(&out[3 * MD + row], y3);
        }
    }
}

extern "C" void kernel_launch(void* const* d_in, const int* in_sizes, int n_in,
                              void* d_out, int out_size)
{
    const float* x    = (const float*)d_in[0];
    const int*   qw   = (const int*)d_in[1];
    const float* am   = (const float*)d_in[2];
    const float* code = (const float*)d_in[3];
    const float* bias = (const float*)d_in[4];
    float*       out  = (float*)d_out;

    cudaMemsetAsync(out, 0, (size_t)out_size * sizeof(float));
    dim3 grid(NSPLIT, MD / RPB);              // (2, 512) = 1024 blocks
    fp4_main<<<grid, WPB * 32>>>(x, qw, am, code, bias, out);
}